// round 3
// baseline (speedup 1.0000x reference)
#include <cuda_runtime.h>
#include <math.h>

#define TQ 4096   // tokens
#define HD 1024   // hidden
#define NE 8      // experts
#define FD 4096   // ffn inner (per half)
#define N1 8192   // 2*FD
#define CAP 4096  // max assignments per expert (token appears at most once per expert)

// ---------------- device scratch (static, no allocation) ----------------
__device__ int   g_cnt[NE];
__device__ int   g_top1[NE];
__device__ int   g_off[NE];
__device__ int   g_tok[NE * CAP];
__device__ float g_wt[NE * CAP];
__device__ float g_probs[TQ * NE];
__device__ float g_h[(size_t)2 * TQ * FD];   // 8192 x 4096 f32 = 128 MB

// ---------------- kernels ----------------
__global__ void zero_kernel() {
    if (threadIdx.x < NE) { g_cnt[threadIdx.x] = 0; g_top1[threadIdx.x] = 0; }
}

__global__ __launch_bounds__(256) void gate_kernel(
    const float* __restrict__ x, const float* __restrict__ gw,
    const float* __restrict__ gb)
{
    __shared__ float s_gw[NE * HD];   // 32 KB
    for (int i = threadIdx.x; i < NE * HD; i += 256) s_gw[i] = gw[i];
    __syncthreads();

    int warp = (blockIdx.x * 256 + threadIdx.x) >> 5;  // token id
    int lane = threadIdx.x & 31;
    const float* xr = x + (size_t)warp * HD;

    float acc[NE];
#pragma unroll
    for (int e = 0; e < NE; e++) acc[e] = 0.f;
    for (int h = lane; h < HD; h += 32) {
        float xv = xr[h];
#pragma unroll
        for (int e = 0; e < NE; e++) acc[e] += xv * s_gw[e * HD + h];
    }
#pragma unroll
    for (int off = 16; off; off >>= 1)
#pragma unroll
        for (int e = 0; e < NE; e++) acc[e] += __shfl_xor_sync(0xffffffffu, acc[e], off);

    if (lane == 0) {
        float lg[NE];
        float mx = -1e30f;
#pragma unroll
        for (int e = 0; e < NE; e++) { lg[e] = acc[e] + gb[e]; mx = fmaxf(mx, lg[e]); }
        float s = 0.f;
#pragma unroll
        for (int e = 0; e < NE; e++) { lg[e] = expf(lg[e] - mx); s += lg[e]; }
        float inv = 1.f / s;
        float p[NE];
#pragma unroll
        for (int e = 0; e < NE; e++) { p[e] = lg[e] * inv; g_probs[warp * NE + e] = p[e]; }

        // top-2 (ties -> lower index, matches jax top_k)
        int e0 = 0; float p0 = p[0];
#pragma unroll
        for (int e = 1; e < NE; e++) if (p[e] > p0) { p0 = p[e]; e0 = e; }
        int e1 = -1; float p1 = -1.f;
#pragma unroll
        for (int e = 0; e < NE; e++) if (e != e0 && p[e] > p1) { p1 = p[e]; e1 = e; }

        atomicAdd(&g_top1[e0], 1);
        float dn = p0 + p1;
        float w0 = p0 / dn, w1 = p1 / dn;
        int s0 = atomicAdd(&g_cnt[e0], 1);
        g_tok[e0 * CAP + s0] = warp; g_wt[e0 * CAP + s0] = w0;
        int s1 = atomicAdd(&g_cnt[e1], 1);
        g_tok[e1 * CAP + s1] = warp; g_wt[e1 * CAP + s1] = w1;
    }
}

// deterministic loss + expert offsets (single block, fixed-order reduction)
__global__ __launch_bounds__(256) void loss_kernel(float* __restrict__ out, int out_size) {
    __shared__ float red[256];
    __shared__ float psum[NE];
    int tid = threadIdx.x;
    for (int e = 0; e < NE; e++) {
        float s = 0.f;
        for (int t = tid; t < TQ; t += 256) s += g_probs[t * NE + e];
        red[tid] = s; __syncthreads();
        for (int o = 128; o; o >>= 1) { if (tid < o) red[tid] += red[tid + o]; __syncthreads(); }
        if (tid == 0) psum[e] = red[0];
        __syncthreads();
    }
    if (tid == 0) {
        int off = 0; float loss = 0.f;
        for (int e = 0; e < NE; e++) {
            g_off[e] = off; off += g_cnt[e];
            loss += (psum[e] / (float)TQ) * ((float)g_top1[e] / (float)TQ);
        }
        loss = loss * (float)(NE * NE) / (float)NE;   // mean over E, times E*E
        if (out_size > TQ * HD) out[(size_t)TQ * HD] = loss;
    }
}

__device__ __forceinline__ float gelu_tanh(float v) {
    float c = 0.7978845608028654f * (v + 0.044715f * v * v * v);
    return 0.5f * v * (1.f + tanhf(c));
}

// GEMM1: h[assign, FD] = gelu(x@w1_gate^T + b1_g) * (x@w1_up^T + b1_u)
// tile: 128(M) x 64(N) x 16(K), 256 threads, 8x4 per-thread per half
__global__ __launch_bounds__(256) void gemm1_kernel(
    const float* __restrict__ x, const float* __restrict__ w1,
    const float* __restrict__ b1)
{
    int e = blockIdx.z;
    int cnt = g_cnt[e];
    int m0 = blockIdx.y * 128;
    if (m0 >= cnt) return;
    int nt = blockIdx.x;           // 0..63 over FD
    int off = g_off[e];

    __shared__ float sA[16][128];
    __shared__ float sBg[16][64];
    __shared__ float sBu[16][64];
    __shared__ int   s_tok[128];

    int tid = threadIdx.x;
    if (tid < 128) {
        int m = m0 + tid;
        s_tok[tid] = (m < cnt) ? g_tok[e * CAP + m] : 0;
    }
    __syncthreads();

    const float* w1g = w1 + (size_t)e * N1 * HD + (size_t)(nt * 64) * HD;
    const float* w1u = w1g + (size_t)FD * HD;

    int ty = tid >> 4, tx = tid & 15;
    float cg[8][4], cu[8][4];
#pragma unroll
    for (int r = 0; r < 8; r++)
#pragma unroll
        for (int c = 0; c < 4; c++) { cg[r][c] = 0.f; cu[r][c] = 0.f; }

    for (int k0 = 0; k0 < HD; k0 += 16) {
#pragma unroll
        for (int t = 0; t < 2; t++) {
            int task = tid + t * 256;
            int row = task & 127, kq = task >> 7;
            int m = m0 + row;
            float4 v = make_float4(0.f, 0.f, 0.f, 0.f);
            if (m < cnt) v = *(const float4*)(x + (size_t)s_tok[row] * HD + k0 + kq * 4);
            sA[kq * 4 + 0][row] = v.x; sA[kq * 4 + 1][row] = v.y;
            sA[kq * 4 + 2][row] = v.z; sA[kq * 4 + 3][row] = v.w;
        }
        {
            int col = tid & 63, kq = tid >> 6;
            float4 v = *(const float4*)(w1g + (size_t)col * HD + k0 + kq * 4);
            sBg[kq * 4 + 0][col] = v.x; sBg[kq * 4 + 1][col] = v.y;
            sBg[kq * 4 + 2][col] = v.z; sBg[kq * 4 + 3][col] = v.w;
            float4 u = *(const float4*)(w1u + (size_t)col * HD + k0 + kq * 4);
            sBu[kq * 4 + 0][col] = u.x; sBu[kq * 4 + 1][col] = u.y;
            sBu[kq * 4 + 2][col] = u.z; sBu[kq * 4 + 3][col] = u.w;
        }
        __syncthreads();
#pragma unroll
        for (int k = 0; k < 16; k++) {
            float a[8], bg[4], bu[4];
            *(float4*)&a[0] = *(const float4*)&sA[k][ty * 8];
            *(float4*)&a[4] = *(const float4*)&sA[k][ty * 8 + 4];
            *(float4*)&bg[0] = *(const float4*)&sBg[k][tx * 4];
            *(float4*)&bu[0] = *(const float4*)&sBu[k][tx * 4];
#pragma unroll
            for (int r = 0; r < 8; r++)
#pragma unroll
                for (int c = 0; c < 4; c++) {
                    cg[r][c] += a[r] * bg[c];
                    cu[r][c] += a[r] * bu[c];
                }
        }
        __syncthreads();
    }

    int nb = nt * 64 + tx * 4;
    float4 b1g = *(const float4*)(b1 + (size_t)e * N1 + nb);
    float4 b1u = *(const float4*)(b1 + (size_t)e * N1 + FD + nb);
#pragma unroll
    for (int r = 0; r < 8; r++) {
        int m = m0 + ty * 8 + r;
        if (m < cnt) {
            float4 hv;
            hv.x = gelu_tanh(cg[r][0] + b1g.x) * (cu[r][0] + b1u.x);
            hv.y = gelu_tanh(cg[r][1] + b1g.y) * (cu[r][1] + b1u.y);
            hv.z = gelu_tanh(cg[r][2] + b1g.z) * (cu[r][2] + b1u.z);
            hv.w = gelu_tanh(cg[r][3] + b1g.w) * (cu[r][3] + b1u.w);
            *(float4*)(&g_h[(size_t)(off + m) * FD + nb]) = hv;
        }
    }
}

// GEMM2: out[token] += weight * (h @ w2^T + b2). Exactly 2 atomic adds per element
// (commutative) => deterministic.
__global__ __launch_bounds__(256) void gemm2_kernel(
    const float* __restrict__ w2, const float* __restrict__ b2,
    float* __restrict__ out)
{
    int e = blockIdx.z;
    int cnt = g_cnt[e];
    int m0 = blockIdx.y * 128;
    if (m0 >= cnt) return;
    int nt = blockIdx.x;           // 0..15 over HD
    int off = g_off[e];

    __shared__ float sA[16][128];
    __shared__ float sB[16][64];
    __shared__ int   s_tok[128];
    __shared__ float s_w[128];

    int tid = threadIdx.x;
    if (tid < 128) {
        int m = m0 + tid;
        s_tok[tid] = (m < cnt) ? g_tok[e * CAP + m] : 0;
        s_w[tid]   = (m < cnt) ? g_wt[e * CAP + m] : 0.f;
    }
    __syncthreads();

    const float* w2g = w2 + ((size_t)e * HD + nt * 64) * FD;

    int ty = tid >> 4, tx = tid & 15;
    float cc[8][4];
#pragma unroll
    for (int r = 0; r < 8; r++)
#pragma unroll
        for (int c = 0; c < 4; c++) cc[r][c] = 0.f;

    for (int k0 = 0; k0 < FD; k0 += 16) {
#pragma unroll
        for (int t = 0; t < 2; t++) {
            int task = tid + t * 256;
            int row = task & 127, kq = task >> 7;
            int m = m0 + row;
            float4 v = make_float4(0.f, 0.f, 0.f, 0.f);
            if (m < cnt) v = *(const float4*)(&g_h[(size_t)(off + m) * FD + k0 + kq * 4]);
            sA[kq * 4 + 0][row] = v.x; sA[kq * 4 + 1][row] = v.y;
            sA[kq * 4 + 2][row] = v.z; sA[kq * 4 + 3][row] = v.w;
        }
        {
            int col = tid & 63, kq = tid >> 6;
            float4 v = *(const float4*)(w2g + (size_t)col * FD + k0 + kq * 4);
            sB[kq * 4 + 0][col] = v.x; sB[kq * 4 + 1][col] = v.y;
            sB[kq * 4 + 2][col] = v.z; sB[kq * 4 + 3][col] = v.w;
        }
        __syncthreads();
#pragma unroll
        for (int k = 0; k < 16; k++) {
            float a[8], b[4];
            *(float4*)&a[0] = *(const float4*)&sA[k][ty * 8];
            *(float4*)&a[4] = *(const float4*)&sA[k][ty * 8 + 4];
            *(float4*)&b[0] = *(const float4*)&sB[k][tx * 4];
#pragma unroll
            for (int r = 0; r < 8; r++)
#pragma unroll
                for (int c = 0; c < 4; c++) cc[r][c] += a[r] * b[c];
        }
        __syncthreads();
    }

    int nb = nt * 64 + tx * 4;
    float4 bb = *(const float4*)(b2 + (size_t)e * HD + nb);
#pragma unroll
    for (int r = 0; r < 8; r++) {
        int m = m0 + ty * 8 + r;
        if (m < cnt) {
            int token = s_tok[ty * 8 + r];
            float w = s_w[ty * 8 + r];
            float* op = out + (size_t)token * HD + nb;
            atomicAdd(op + 0, w * (cc[r][0] + bb.x));
            atomicAdd(op + 1, w * (cc[r][1] + bb.y));
            atomicAdd(op + 2, w * (cc[r][2] + bb.z));
            atomicAdd(op + 3, w * (cc[r][3] + bb.w));
        }
    }
}

// ---------------- launch ----------------
extern "C" void kernel_launch(void* const* d_in, const int* in_sizes, int n_in,
                              void* d_out, int out_size)
{
    const float* x  = (const float*)d_in[0];
    const float* gw = (const float*)d_in[1];
    const float* gb = (const float*)d_in[2];
    const float* w1 = (const float*)d_in[3];
    const float* b1 = (const float*)d_in[4];
    const float* w2 = (const float*)d_in[5];
    const float* b2 = (const float*)d_in[6];
    float* out = (float*)d_out;

    zero_kernel<<<1, 32>>>();
    cudaMemsetAsync(d_out, 0, (size_t)TQ * HD * sizeof(float), 0);
    gate_kernel<<<TQ / 8, 256>>>(x, gw, gb);
    loss_kernel<<<1, 256>>>(out, out_size);

    dim3 g1(FD / 64, CAP / 128, NE);   // 64 x 32 x 8; empty tiles early-exit
    gemm1_kernel<<<g1, 256>>>(x, w1, b1);

    dim3 g2(HD / 64, CAP / 128, NE);   // 16 x 32 x 8
    gemm2_kernel<<<g2, 256>>>(w2, b2, out);
}

// round 4
// speedup vs baseline: 1.0025x; 1.0025x over previous
#include <cuda_runtime.h>
#include <math.h>

#define TQ 4096   // tokens
#define HD 1024   // hidden
#define NE 8      // experts
#define FD 4096   // ffn inner (per half)
#define N1 8192   // 2*FD
#define CAP 4096  // max assignments per expert (token appears at most once per expert)

// ---------------- device scratch (static, no allocation) ----------------
__device__ int   g_cnt[NE];
__device__ int   g_top1[NE];
__device__ int   g_off[NE];
__device__ int   g_tok[NE * CAP];
__device__ float g_wt[NE * CAP];
__device__ float g_probs[TQ * NE];
__device__ float g_h[(size_t)2 * TQ * FD];   // 8192 x 4096 f32 = 128 MB

// ---------------- kernels ----------------
__global__ void zero_kernel() {
    if (threadIdx.x < NE) { g_cnt[threadIdx.x] = 0; g_top1[threadIdx.x] = 0; }
}

__global__ __launch_bounds__(256) void gate_kernel(
    const float* __restrict__ x, const float* __restrict__ gw,
    const float* __restrict__ gb)
{
    __shared__ float s_gw[NE * HD];   // 32 KB
    for (int i = threadIdx.x; i < NE * HD; i += 256) s_gw[i] = gw[i];
    __syncthreads();

    int warp = (blockIdx.x * 256 + threadIdx.x) >> 5;  // token id
    int lane = threadIdx.x & 31;
    const float* xr = x + (size_t)warp * HD;

    float acc[NE];
#pragma unroll
    for (int e = 0; e < NE; e++) acc[e] = 0.f;
    for (int h = lane; h < HD; h += 32) {
        float xv = xr[h];
#pragma unroll
        for (int e = 0; e < NE; e++) acc[e] += xv * s_gw[e * HD + h];
    }
#pragma unroll
    for (int off = 16; off; off >>= 1)
#pragma unroll
        for (int e = 0; e < NE; e++) acc[e] += __shfl_xor_sync(0xffffffffu, acc[e], off);

    if (lane == 0) {
        float lg[NE];
        float mx = -1e30f;
#pragma unroll
        for (int e = 0; e < NE; e++) { lg[e] = acc[e] + gb[e]; mx = fmaxf(mx, lg[e]); }
        float s = 0.f;
#pragma unroll
        for (int e = 0; e < NE; e++) { lg[e] = expf(lg[e] - mx); s += lg[e]; }
        float inv = 1.f / s;
        float p[NE];
#pragma unroll
        for (int e = 0; e < NE; e++) { p[e] = lg[e] * inv; g_probs[warp * NE + e] = p[e]; }

        // top-2 (ties -> lower index, matches jax top_k)
        int e0 = 0; float p0 = p[0];
#pragma unroll
        for (int e = 1; e < NE; e++) if (p[e] > p0) { p0 = p[e]; e0 = e; }
        int e1 = -1; float p1 = -1.f;
#pragma unroll
        for (int e = 0; e < NE; e++) if (e != e0 && p[e] > p1) { p1 = p[e]; e1 = e; }

        atomicAdd(&g_top1[e0], 1);
        float dn = p0 + p1;
        float w0 = p0 / dn, w1 = p1 / dn;
        int s0 = atomicAdd(&g_cnt[e0], 1);
        g_tok[e0 * CAP + s0] = warp; g_wt[e0 * CAP + s0] = w0;
        int s1 = atomicAdd(&g_cnt[e1], 1);
        g_tok[e1 * CAP + s1] = warp; g_wt[e1 * CAP + s1] = w1;
    }
}

// deterministic loss + expert offsets (single block, fixed-order reduction)
__global__ __launch_bounds__(256) void loss_kernel(float* __restrict__ out, int out_size) {
    __shared__ float red[256];
    __shared__ float psum[NE];
    int tid = threadIdx.x;
    for (int e = 0; e < NE; e++) {
        float s = 0.f;
        for (int t = tid; t < TQ; t += 256) s += g_probs[t * NE + e];
        red[tid] = s; __syncthreads();
        for (int o = 128; o; o >>= 1) { if (tid < o) red[tid] += red[tid + o]; __syncthreads(); }
        if (tid == 0) psum[e] = red[0];
        __syncthreads();
    }
    if (tid == 0) {
        int off = 0; float loss = 0.f;
        for (int e = 0; e < NE; e++) {
            g_off[e] = off; off += g_cnt[e];
            loss += (psum[e] / (float)TQ) * ((float)g_top1[e] / (float)TQ);
        }
        loss = loss * (float)(NE * NE) / (float)NE;   // mean over E, times E*E
        if (out_size > TQ * HD) out[(size_t)TQ * HD] = loss;
    }
}

__device__ __forceinline__ float gelu_tanh(float v) {
    float c = 0.7978845608028654f * (v + 0.044715f * v * v * v);
    return 0.5f * v * (1.f + tanhf(c));
}

// GEMM1: h[assign, FD] = gelu(x@w1_gate^T + b1_g) * (x@w1_up^T + b1_u)
// tile: 128(M) x 64(N) x 16(K), 256 threads, 8x4 per-thread per half
__global__ __launch_bounds__(256) void gemm1_kernel(
    const float* __restrict__ x, const float* __restrict__ w1,
    const float* __restrict__ b1)
{
    int e = blockIdx.z;
    int cnt = g_cnt[e];
    int m0 = blockIdx.y * 128;
    if (m0 >= cnt) return;
    int nt = blockIdx.x;           // 0..63 over FD
    int off = g_off[e];

    __shared__ float sA[16][128];
    __shared__ float sBg[16][64];
    __shared__ float sBu[16][64];
    __shared__ int   s_tok[128];

    int tid = threadIdx.x;
    if (tid < 128) {
        int m = m0 + tid;
        s_tok[tid] = (m < cnt) ? g_tok[e * CAP + m] : 0;
    }
    __syncthreads();

    const float* w1g = w1 + (size_t)e * N1 * HD + (size_t)(nt * 64) * HD;
    const float* w1u = w1g + (size_t)FD * HD;

    int ty = tid >> 4, tx = tid & 15;
    float cg[8][4], cu[8][4];
#pragma unroll
    for (int r = 0; r < 8; r++)
#pragma unroll
        for (int c = 0; c < 4; c++) { cg[r][c] = 0.f; cu[r][c] = 0.f; }

    for (int k0 = 0; k0 < HD; k0 += 16) {
#pragma unroll
        for (int t = 0; t < 2; t++) {
            int task = tid + t * 256;
            int row = task & 127, kq = task >> 7;
            int m = m0 + row;
            float4 v = make_float4(0.f, 0.f, 0.f, 0.f);
            if (m < cnt) v = *(const float4*)(x + (size_t)s_tok[row] * HD + k0 + kq * 4);
            sA[kq * 4 + 0][row] = v.x; sA[kq * 4 + 1][row] = v.y;
            sA[kq * 4 + 2][row] = v.z; sA[kq * 4 + 3][row] = v.w;
        }
        {
            int col = tid & 63, kq = tid >> 6;
            float4 v = *(const float4*)(w1g + (size_t)col * HD + k0 + kq * 4);
            sBg[kq * 4 + 0][col] = v.x; sBg[kq * 4 + 1][col] = v.y;
            sBg[kq * 4 + 2][col] = v.z; sBg[kq * 4 + 3][col] = v.w;
            float4 u = *(const float4*)(w1u + (size_t)col * HD + k0 + kq * 4);
            sBu[kq * 4 + 0][col] = u.x; sBu[kq * 4 + 1][col] = u.y;
            sBu[kq * 4 + 2][col] = u.z; sBu[kq * 4 + 3][col] = u.w;
        }
        __syncthreads();
#pragma unroll
        for (int k = 0; k < 16; k++) {
            float a[8], bg[4], bu[4];
            *(float4*)&a[0] = *(const float4*)&sA[k][ty * 8];
            *(float4*)&a[4] = *(const float4*)&sA[k][ty * 8 + 4];
            *(float4*)&bg[0] = *(const float4*)&sBg[k][tx * 4];
            *(float4*)&bu[0] = *(const float4*)&sBu[k][tx * 4];
#pragma unroll
            for (int r = 0; r < 8; r++)
#pragma unroll
                for (int c = 0; c < 4; c++) {
                    cg[r][c] += a[r] * bg[c];
                    cu[r][c] += a[r] * bu[c];
                }
        }
        __syncthreads();
    }

    int nb = nt * 64 + tx * 4;
    float4 b1g = *(const float4*)(b1 + (size_t)e * N1 + nb);
    float4 b1u = *(const float4*)(b1 + (size_t)e * N1 + FD + nb);
#pragma unroll
    for (int r = 0; r < 8; r++) {
        int m = m0 + ty * 8 + r;
        if (m < cnt) {
            float4 hv;
            hv.x = gelu_tanh(cg[r][0] + b1g.x) * (cu[r][0] + b1u.x);
            hv.y = gelu_tanh(cg[r][1] + b1g.y) * (cu[r][1] + b1u.y);
            hv.z = gelu_tanh(cg[r][2] + b1g.z) * (cu[r][2] + b1u.z);
            hv.w = gelu_tanh(cg[r][3] + b1g.w) * (cu[r][3] + b1u.w);
            *(float4*)(&g_h[(size_t)(off + m) * FD + nb]) = hv;
        }
    }
}

// GEMM2: out[token] += weight * (h @ w2^T + b2). Exactly 2 atomic adds per element
// (commutative) => deterministic.
__global__ __launch_bounds__(256) void gemm2_kernel(
    const float* __restrict__ w2, const float* __restrict__ b2,
    float* __restrict__ out)
{
    int e = blockIdx.z;
    int cnt = g_cnt[e];
    int m0 = blockIdx.y * 128;
    if (m0 >= cnt) return;
    int nt = blockIdx.x;           // 0..15 over HD
    int off = g_off[e];

    __shared__ float sA[16][128];
    __shared__ float sB[16][64];
    __shared__ int   s_tok[128];
    __shared__ float s_w[128];

    int tid = threadIdx.x;
    if (tid < 128) {
        int m = m0 + tid;
        s_tok[tid] = (m < cnt) ? g_tok[e * CAP + m] : 0;
        s_w[tid]   = (m < cnt) ? g_wt[e * CAP + m] : 0.f;
    }
    __syncthreads();

    const float* w2g = w2 + ((size_t)e * HD + nt * 64) * FD;

    int ty = tid >> 4, tx = tid & 15;
    float cc[8][4];
#pragma unroll
    for (int r = 0; r < 8; r++)
#pragma unroll
        for (int c = 0; c < 4; c++) cc[r][c] = 0.f;

    for (int k0 = 0; k0 < FD; k0 += 16) {
#pragma unroll
        for (int t = 0; t < 2; t++) {
            int task = tid + t * 256;
            int row = task & 127, kq = task >> 7;
            int m = m0 + row;
            float4 v = make_float4(0.f, 0.f, 0.f, 0.f);
            if (m < cnt) v = *(const float4*)(&g_h[(size_t)(off + m) * FD + k0 + kq * 4]);
            sA[kq * 4 + 0][row] = v.x; sA[kq * 4 + 1][row] = v.y;
            sA[kq * 4 + 2][row] = v.z; sA[kq * 4 + 3][row] = v.w;
        }
        {
            int col = tid & 63, kq = tid >> 6;
            float4 v = *(const float4*)(w2g + (size_t)col * FD + k0 + kq * 4);
            sB[kq * 4 + 0][col] = v.x; sB[kq * 4 + 1][col] = v.y;
            sB[kq * 4 + 2][col] = v.z; sB[kq * 4 + 3][col] = v.w;
        }
        __syncthreads();
#pragma unroll
        for (int k = 0; k < 16; k++) {
            float a[8], b[4];
            *(float4*)&a[0] = *(const float4*)&sA[k][ty * 8];
            *(float4*)&a[4] = *(const float4*)&sA[k][ty * 8 + 4];
            *(float4*)&b[0] = *(const float4*)&sB[k][tx * 4];
#pragma unroll
            for (int r = 0; r < 8; r++)
#pragma unroll
                for (int c = 0; c < 4; c++) cc[r][c] += a[r] * b[c];
        }
        __syncthreads();
    }

    int nb = nt * 64 + tx * 4;
    float4 bb = *(const float4*)(b2 + (size_t)e * HD + nb);
#pragma unroll
    for (int r = 0; r < 8; r++) {
        int m = m0 + ty * 8 + r;
        if (m < cnt) {
            int token = s_tok[ty * 8 + r];
            float w = s_w[ty * 8 + r];
            float* op = out + (size_t)token * HD + nb;
            atomicAdd(op + 0, w * (cc[r][0] + bb.x));
            atomicAdd(op + 1, w * (cc[r][1] + bb.y));
            atomicAdd(op + 2, w * (cc[r][2] + bb.z));
            atomicAdd(op + 3, w * (cc[r][3] + bb.w));
        }
    }
}

// ---------------- launch ----------------
extern "C" void kernel_launch(void* const* d_in, const int* in_sizes, int n_in,
                              void* d_out, int out_size)
{
    const float* x  = (const float*)d_in[0];
    const float* gw = (const float*)d_in[1];
    const float* gb = (const float*)d_in[2];
    const float* w1 = (const float*)d_in[3];
    const float* b1 = (const float*)d_in[4];
    const float* w2 = (const float*)d_in[5];
    const float* b2 = (const float*)d_in[6];
    float* out = (float*)d_out;

    zero_kernel<<<1, 32>>>();
    cudaMemsetAsync(d_out, 0, (size_t)TQ * HD * sizeof(float), 0);
    gate_kernel<<<TQ / 8, 256>>>(x, gw, gb);
    loss_kernel<<<1, 256>>>(out, out_size);

    dim3 g1(FD / 64, CAP / 128, NE);   // 64 x 32 x 8; empty tiles early-exit
    gemm1_kernel<<<g1, 256>>>(x, w1, b1);

    dim3 g2(HD / 64, CAP / 128, NE);   // 16 x 32 x 8
    gemm2_kernel<<<g2, 256>>>(w2, b2, out);
}

// round 5
// speedup vs baseline: 1.0046x; 1.0021x over previous
#include <cuda_runtime.h>
#include <math.h>

#define TQ 4096   // tokens
#define HD 1024   // hidden
#define NE 8      // experts
#define FD 4096   // ffn inner (per half)
#define N1 8192   // 2*FD
#define CAP 4096  // max assignments per expert (token appears at most once per expert)

// ---------------- device scratch (static, no allocation) ----------------
__device__ int   g_cnt[NE];
__device__ int   g_top1[NE];
__device__ int   g_off[NE];
__device__ int   g_tok[NE * CAP];
__device__ float g_wt[NE * CAP];
__device__ float g_probs[TQ * NE];
__device__ float g_h[(size_t)2 * TQ * FD];   // 8192 x 4096 f32 = 128 MB

// ---------------- kernels ----------------
__global__ void zero_kernel() {
    if (threadIdx.x < NE) { g_cnt[threadIdx.x] = 0; g_top1[threadIdx.x] = 0; }
}

__global__ __launch_bounds__(256) void gate_kernel(
    const float* __restrict__ x, const float* __restrict__ gw,
    const float* __restrict__ gb)
{
    __shared__ float s_gw[NE * HD];   // 32 KB
    for (int i = threadIdx.x; i < NE * HD; i += 256) s_gw[i] = gw[i];
    __syncthreads();

    int warp = (blockIdx.x * 256 + threadIdx.x) >> 5;  // token id
    int lane = threadIdx.x & 31;
    const float* xr = x + (size_t)warp * HD;

    float acc[NE];
#pragma unroll
    for (int e = 0; e < NE; e++) acc[e] = 0.f;
    for (int h = lane; h < HD; h += 32) {
        float xv = xr[h];
#pragma unroll
        for (int e = 0; e < NE; e++) acc[e] += xv * s_gw[e * HD + h];
    }
#pragma unroll
    for (int off = 16; off; off >>= 1)
#pragma unroll
        for (int e = 0; e < NE; e++) acc[e] += __shfl_xor_sync(0xffffffffu, acc[e], off);

    if (lane == 0) {
        float lg[NE];
        float mx = -1e30f;
#pragma unroll
        for (int e = 0; e < NE; e++) { lg[e] = acc[e] + gb[e]; mx = fmaxf(mx, lg[e]); }
        float s = 0.f;
#pragma unroll
        for (int e = 0; e < NE; e++) { lg[e] = expf(lg[e] - mx); s += lg[e]; }
        float inv = 1.f / s;
        float p[NE];
#pragma unroll
        for (int e = 0; e < NE; e++) { p[e] = lg[e] * inv; g_probs[warp * NE + e] = p[e]; }

        // top-2 (ties -> lower index, matches jax top_k)
        int e0 = 0; float p0 = p[0];
#pragma unroll
        for (int e = 1; e < NE; e++) if (p[e] > p0) { p0 = p[e]; e0 = e; }
        int e1 = -1; float p1 = -1.f;
#pragma unroll
        for (int e = 0; e < NE; e++) if (e != e0 && p[e] > p1) { p1 = p[e]; e1 = e; }

        atomicAdd(&g_top1[e0], 1);
        float dn = p0 + p1;
        float w0 = p0 / dn, w1 = p1 / dn;
        int s0 = atomicAdd(&g_cnt[e0], 1);
        g_tok[e0 * CAP + s0] = warp; g_wt[e0 * CAP + s0] = w0;
        int s1 = atomicAdd(&g_cnt[e1], 1);
        g_tok[e1 * CAP + s1] = warp; g_wt[e1 * CAP + s1] = w1;
    }
}

// deterministic loss + expert offsets (single block, fixed-order reduction)
__global__ __launch_bounds__(256) void loss_kernel(float* __restrict__ out, int out_size) {
    __shared__ float red[256];
    __shared__ float psum[NE];
    int tid = threadIdx.x;
    for (int e = 0; e < NE; e++) {
        float s = 0.f;
        for (int t = tid; t < TQ; t += 256) s += g_probs[t * NE + e];
        red[tid] = s; __syncthreads();
        for (int o = 128; o; o >>= 1) { if (tid < o) red[tid] += red[tid + o]; __syncthreads(); }
        if (tid == 0) psum[e] = red[0];
        __syncthreads();
    }
    if (tid == 0) {
        int off = 0; float loss = 0.f;
        for (int e = 0; e < NE; e++) {
            g_off[e] = off; off += g_cnt[e];
            loss += (psum[e] / (float)TQ) * ((float)g_top1[e] / (float)TQ);
        }
        loss = loss * (float)(NE * NE) / (float)NE;   // mean over E, times E*E
        if (out_size > TQ * HD) out[(size_t)TQ * HD] = loss;
    }
}

__device__ __forceinline__ float gelu_tanh(float v) {
    float c = 0.7978845608028654f * (v + 0.044715f * v * v * v);
    return 0.5f * v * (1.f + tanhf(c));
}

// GEMM1: h[assign, FD] = gelu(x@w1_gate^T + b1_g) * (x@w1_up^T + b1_u)
// tile: 128(M) x 64(N) x 16(K), 256 threads, 8x4 per-thread per half
__global__ __launch_bounds__(256) void gemm1_kernel(
    const float* __restrict__ x, const float* __restrict__ w1,
    const float* __restrict__ b1)
{
    int e = blockIdx.z;
    int cnt = g_cnt[e];
    int m0 = blockIdx.y * 128;
    if (m0 >= cnt) return;
    int nt = blockIdx.x;           // 0..63 over FD
    int off = g_off[e];

    __shared__ float sA[16][128];
    __shared__ float sBg[16][64];
    __shared__ float sBu[16][64];
    __shared__ int   s_tok[128];

    int tid = threadIdx.x;
    if (tid < 128) {
        int m = m0 + tid;
        s_tok[tid] = (m < cnt) ? g_tok[e * CAP + m] : 0;
    }
    __syncthreads();

    const float* w1g = w1 + (size_t)e * N1 * HD + (size_t)(nt * 64) * HD;
    const float* w1u = w1g + (size_t)FD * HD;

    int ty = tid >> 4, tx = tid & 15;
    float cg[8][4], cu[8][4];
#pragma unroll
    for (int r = 0; r < 8; r++)
#pragma unroll
        for (int c = 0; c < 4; c++) { cg[r][c] = 0.f; cu[r][c] = 0.f; }

    for (int k0 = 0; k0 < HD; k0 += 16) {
#pragma unroll
        for (int t = 0; t < 2; t++) {
            int task = tid + t * 256;
            int row = task & 127, kq = task >> 7;
            int m = m0 + row;
            float4 v = make_float4(0.f, 0.f, 0.f, 0.f);
            if (m < cnt) v = *(const float4*)(x + (size_t)s_tok[row] * HD + k0 + kq * 4);
            sA[kq * 4 + 0][row] = v.x; sA[kq * 4 + 1][row] = v.y;
            sA[kq * 4 + 2][row] = v.z; sA[kq * 4 + 3][row] = v.w;
        }
        {
            int col = tid & 63, kq = tid >> 6;
            float4 v = *(const float4*)(w1g + (size_t)col * HD + k0 + kq * 4);
            sBg[kq * 4 + 0][col] = v.x; sBg[kq * 4 + 1][col] = v.y;
            sBg[kq * 4 + 2][col] = v.z; sBg[kq * 4 + 3][col] = v.w;
            float4 u = *(const float4*)(w1u + (size_t)col * HD + k0 + kq * 4);
            sBu[kq * 4 + 0][col] = u.x; sBu[kq * 4 + 1][col] = u.y;
            sBu[kq * 4 + 2][col] = u.z; sBu[kq * 4 + 3][col] = u.w;
        }
        __syncthreads();
#pragma unroll
        for (int k = 0; k < 16; k++) {
            float a[8], bg[4], bu[4];
            *(float4*)&a[0] = *(const float4*)&sA[k][ty * 8];
            *(float4*)&a[4] = *(const float4*)&sA[k][ty * 8 + 4];
            *(float4*)&bg[0] = *(const float4*)&sBg[k][tx * 4];
            *(float4*)&bu[0] = *(const float4*)&sBu[k][tx * 4];
#pragma unroll
            for (int r = 0; r < 8; r++)
#pragma unroll
                for (int c = 0; c < 4; c++) {
                    cg[r][c] += a[r] * bg[c];
                    cu[r][c] += a[r] * bu[c];
                }
        }
        __syncthreads();
    }

    int nb = nt * 64 + tx * 4;
    float4 b1g = *(const float4*)(b1 + (size_t)e * N1 + nb);
    float4 b1u = *(const float4*)(b1 + (size_t)e * N1 + FD + nb);
#pragma unroll
    for (int r = 0; r < 8; r++) {
        int m = m0 + ty * 8 + r;
        if (m < cnt) {
            float4 hv;
            hv.x = gelu_tanh(cg[r][0] + b1g.x) * (cu[r][0] + b1u.x);
            hv.y = gelu_tanh(cg[r][1] + b1g.y) * (cu[r][1] + b1u.y);
            hv.z = gelu_tanh(cg[r][2] + b1g.z) * (cu[r][2] + b1u.z);
            hv.w = gelu_tanh(cg[r][3] + b1g.w) * (cu[r][3] + b1u.w);
            *(float4*)(&g_h[(size_t)(off + m) * FD + nb]) = hv;
        }
    }
}

// GEMM2: out[token] += weight * (h @ w2^T + b2). Exactly 2 atomic adds per element
// (commutative) => deterministic.
__global__ __launch_bounds__(256) void gemm2_kernel(
    const float* __restrict__ w2, const float* __restrict__ b2,
    float* __restrict__ out)
{
    int e = blockIdx.z;
    int cnt = g_cnt[e];
    int m0 = blockIdx.y * 128;
    if (m0 >= cnt) return;
    int nt = blockIdx.x;           // 0..15 over HD
    int off = g_off[e];

    __shared__ float sA[16][128];
    __shared__ float sB[16][64];
    __shared__ int   s_tok[128];
    __shared__ float s_w[128];

    int tid = threadIdx.x;
    if (tid < 128) {
        int m = m0 + tid;
        s_tok[tid] = (m < cnt) ? g_tok[e * CAP + m] : 0;
        s_w[tid]   = (m < cnt) ? g_wt[e * CAP + m] : 0.f;
    }
    __syncthreads();

    const float* w2g = w2 + ((size_t)e * HD + nt * 64) * FD;

    int ty = tid >> 4, tx = tid & 15;
    float cc[8][4];
#pragma unroll
    for (int r = 0; r < 8; r++)
#pragma unroll
        for (int c = 0; c < 4; c++) cc[r][c] = 0.f;

    for (int k0 = 0; k0 < FD; k0 += 16) {
#pragma unroll
        for (int t = 0; t < 2; t++) {
            int task = tid + t * 256;
            int row = task & 127, kq = task >> 7;
            int m = m0 + row;
            float4 v = make_float4(0.f, 0.f, 0.f, 0.f);
            if (m < cnt) v = *(const float4*)(&g_h[(size_t)(off + m) * FD + k0 + kq * 4]);
            sA[kq * 4 + 0][row] = v.x; sA[kq * 4 + 1][row] = v.y;
            sA[kq * 4 + 2][row] = v.z; sA[kq * 4 + 3][row] = v.w;
        }
        {
            int col = tid & 63, kq = tid >> 6;
            float4 v = *(const float4*)(w2g + (size_t)col * FD + k0 + kq * 4);
            sB[kq * 4 + 0][col] = v.x; sB[kq * 4 + 1][col] = v.y;
            sB[kq * 4 + 2][col] = v.z; sB[kq * 4 + 3][col] = v.w;
        }
        __syncthreads();
#pragma unroll
        for (int k = 0; k < 16; k++) {
            float a[8], b[4];
            *(float4*)&a[0] = *(const float4*)&sA[k][ty * 8];
            *(float4*)&a[4] = *(const float4*)&sA[k][ty * 8 + 4];
            *(float4*)&b[0] = *(const float4*)&sB[k][tx * 4];
#pragma unroll
            for (int r = 0; r < 8; r++)
#pragma unroll
                for (int c = 0; c < 4; c++) cc[r][c] += a[r] * b[c];
        }
        __syncthreads();
    }

    int nb = nt * 64 + tx * 4;
    float4 bb = *(const float4*)(b2 + (size_t)e * HD + nb);
#pragma unroll
    for (int r = 0; r < 8; r++) {
        int m = m0 + ty * 8 + r;
        if (m < cnt) {
            int token = s_tok[ty * 8 + r];
            float w = s_w[ty * 8 + r];
            float* op = out + (size_t)token * HD + nb;
            atomicAdd(op + 0, w * (cc[r][0] + bb.x));
            atomicAdd(op + 1, w * (cc[r][1] + bb.y));
            atomicAdd(op + 2, w * (cc[r][2] + bb.z));
            atomicAdd(op + 3, w * (cc[r][3] + bb.w));
        }
    }
}

// ---------------- launch ----------------
extern "C" void kernel_launch(void* const* d_in, const int* in_sizes, int n_in,
                              void* d_out, int out_size)
{
    const float* x  = (const float*)d_in[0];
    const float* gw = (const float*)d_in[1];
    const float* gb = (const float*)d_in[2];
    const float* w1 = (const float*)d_in[3];
    const float* b1 = (const float*)d_in[4];
    const float* w2 = (const float*)d_in[5];
    const float* b2 = (const float*)d_in[6];
    float* out = (float*)d_out;

    zero_kernel<<<1, 32>>>();
    cudaMemsetAsync(d_out, 0, (size_t)TQ * HD * sizeof(float), 0);
    gate_kernel<<<TQ / 8, 256>>>(x, gw, gb);
    loss_kernel<<<1, 256>>>(out, out_size);

    dim3 g1(FD / 64, CAP / 128, NE);   // 64 x 32 x 8; empty tiles early-exit
    gemm1_kernel<<<g1, 256>>>(x, w1, b1);

    dim3 g2(HD / 64, CAP / 128, NE);   // 16 x 32 x 8
    gemm2_kernel<<<g2, 256>>>(w2, b2, out);
}